// round 3
// baseline (speedup 1.0000x reference)
#include <cuda_runtime.h>

#define TI 128
#define NT 1024
#define MAX_TILES 64
#define MAX_P (MAX_TILES * (MAX_TILES + 1) / 2)

__device__ double       g_part[MAX_P];
__device__ unsigned int g_count;   // zero at load; last block resets each launch

// SIGMA=1 -> a = 1/sqrt(2), a^2 = 0.5, c = 2a/sqrt(pi)
#define C_CONST  0.79788456080286536f
#define PA_CONST 0.23174530376899319f   /* 0.3275911 * a */

// Per-pair interaction; DIAG controls whether the i==j self-mask is applied.
template<bool DIAG>
__device__ __forceinline__ float pair_term(
    float rix, float riy, float riz, float qi,
    float uix, float uiy, float uiz,
    const float4& rqj, const float4& ujv,
    bool self)
{
    float dx = rqj.x - rix;
    float dy = rqj.y - riy;
    float dz = rqj.z - riz;
    float rsq = fmaf(dx, dx, fmaf(dy, dy, dz * dz));

    if (DIAG) { if (self) rsq = 1.0f; }     // keep math finite; masked below

    float rinv  = rsqrtf(rsq);
    float rr    = rsq * rinv;               // |r|
    float gauss = __expf(-0.5f * rsq);      // exp(-(a r)^2)

    // Abramowitz-Stegun 7.1.26 (|err| < 1.5e-7), reuses gauss = e^{-x^2};
    // the 'a' factor is folded into PA_CONST.
    float t = __frcp_rn(fmaf(PA_CONST, rr, 1.0f));
    float poly = fmaf(t, fmaf(t, fmaf(t, fmaf(t, 1.061405429f, -1.453152027f),
                                      1.421413741f), -0.284496736f), 0.254829592f);
    float erfv = fmaf(-t * poly, gauss, 1.0f);

    float rinv2 = rinv * rinv;
    float e1 = erfv * rinv;                          // erf/r
    float e3 = e1 * rinv2;                           // erf/r^3
    float cg = C_CONST * gauss;
    float g2 = cg * rinv2;                           // c*gauss/r^2
    float s1 = e3 - g2;
    float s2 = fmaf(3.0f, e3, fmaf(-2.0f, g2, -cg)); // 3e3 - 2g2 - c*gauss

    float qj  = rqj.w;
    float udi = fmaf(uix, dx, fmaf(uiy, dy, uiz * dz));
    float udj = fmaf(ujv.x, dx, fmaf(ujv.y, dy, ujv.z * dz));
    float uu  = fmaf(uix, ujv.x, fmaf(uiy, ujv.y, uiz * ujv.z));

    float pr = (qi * qj) * e1;                         // qq
    pr = fmaf(-s1, fmaf(qj, udi, -(qi * udj)), pr);    // qu
    pr = fmaf(s1, uu, pr);                             // uu (iso)
    pr = fmaf(-s2, (udi * udj) * rinv2, pr);           // uu (aniso)

    if (DIAG) pr = self ? 0.0f : pr;
    return pr;
}

__global__ void __launch_bounds__(NT) pair_kernel(
    const float* __restrict__ q, const float* __restrict__ r,
    const float* __restrict__ u, int n, int tiles, float outscale,
    float* __restrict__ out)
{
    // ---- triangular tile index -> (bi, bj), bi <= bj ----
    int p = blockIdx.x;
    int bi = 0;
    while (p >= tiles - bi) { p -= tiles - bi; bi++; }
    const int bj = bi + p;
    const bool diag = (bi == bj);

    __shared__ float4 s_rq[TI];   // (x, y, z, q)
    __shared__ float4 s_u[TI];    // (ux, uy, uz, 0)

    const int tx = threadIdx.x;
    const int il = tx & (TI - 1);     // i-lane within tile
    const int jg = tx >> 7;           // j-group 0..7
    const int i  = bi * TI + il;
    const int j0 = bj * TI;

    if (tx < TI) {
        int j = j0 + tx;
        float4 v;
        if (j < n) { v.x = r[3*j]; v.y = r[3*j+1]; v.z = r[3*j+2]; v.w = q[j]; }
        else       { v.x = 1.0e7f + (float)j; v.y = 0.f; v.z = 0.f; v.w = 0.f; }
        s_rq[tx] = v;
    } else if (tx < 2 * TI) {
        int jt = tx - TI;
        int j  = j0 + jt;
        float4 v;
        if (j < n) { v.x = u[3*j]; v.y = u[3*j+1]; v.z = u[3*j+2]; v.w = 0.f; }
        else       { v = make_float4(0.f, 0.f, 0.f, 0.f); }
        s_u[jt] = v;
    }

    float qi = 0.f, rix, riy = 0.f, riz = 0.f, uix = 0.f, uiy = 0.f, uiz = 0.f;
    if (i < n) {
        qi  = q[i];
        rix = r[3*i]; riy = r[3*i+1]; riz = r[3*i+2];
        uix = u[3*i]; uiy = u[3*i+1]; uiz = u[3*i+2];
    } else {
        rix = 2.0e7f + (float)i;   // far, with q=u=0 -> zero contribution
    }
    __syncthreads();

    double acc = 0.0;
    const int jbeg = jg * (TI / 8);    // 16 j's per thread

    if (!diag) {
        #pragma unroll 2
        for (int g = 0; g < TI / 8; g += 8) {
            float facc = 0.0f;
            #pragma unroll
            for (int k = 0; k < 8; k++) {
                int jj = jbeg + g + k;
                facc += pair_term<false>(rix, riy, riz, qi, uix, uiy, uiz,
                                         s_rq[jj], s_u[jj], false);
            }
            acc += (double)facc;
        }
    } else {
        #pragma unroll 2
        for (int g = 0; g < TI / 8; g += 8) {
            float facc = 0.0f;
            #pragma unroll
            for (int k = 0; k < 8; k++) {
                int jj = jbeg + g + k;
                facc += pair_term<true>(rix, riy, riz, qi, uix, uiy, uiz,
                                        s_rq[jj], s_u[jj], (j0 + jj) == i);
            }
            acc += (double)facc;
        }
        acc *= 0.5;   // diagonal tile counts each unordered pair twice
    }

    // ---- deterministic block reduction ----
    #pragma unroll
    for (int off = 16; off > 0; off >>= 1)
        acc += __shfl_down_sync(0xffffffffu, acc, off);

    __shared__ double warp_s[NT / 32];
    if ((tx & 31) == 0) warp_s[tx >> 5] = acc;
    __syncthreads();

    __shared__ bool isLast;
    if (tx == 0) {
        double s = 0.0;
        #pragma unroll
        for (int w = 0; w < NT / 32; w++) s += warp_s[w];
        g_part[blockIdx.x] = s;
        __threadfence();
        unsigned c = atomicAdd(&g_count, 1u);
        isLast = (c == gridDim.x - 1);
    }
    __syncthreads();

    // ---- last block: final reduction (fixed order -> deterministic) ----
    if (isLast) {
        __threadfence();
        const int nP = gridDim.x;
        double s = 0.0;
        for (int k = tx; k < nP; k += NT) s += g_part[k];

        #pragma unroll
        for (int off = 16; off > 0; off >>= 1)
            s += __shfl_down_sync(0xffffffffu, s, off);

        __shared__ double fin_s[NT / 32];
        if ((tx & 31) == 0) fin_s[tx >> 5] = s;
        __syncthreads();
        if (tx == 0) {
            double tot = 0.0;
            #pragma unroll
            for (int w = 0; w < NT / 32; w++) tot += fin_s[w];
            out[0] = (float)(tot * (double)outscale);
            g_count = 0;   // reset for next graph replay
        }
    }
}

extern "C" void kernel_launch(void* const* d_in, const int* in_sizes, int n_in,
                              void* d_out, int out_size)
{
    const float* q = (const float*)d_in[0];
    const float* r = (const float*)d_in[1];
    const float* u = (const float*)d_in[2];
    float* out = (float*)d_out;

    int n = in_sizes[0];
    int tiles = (n + TI - 1) / TI;
    if (tiles > MAX_TILES) tiles = MAX_TILES;

    int nP = tiles * (tiles + 1) / 2;
    float outscale = (float)(90.0474 / 6.283185307179586476925286766559);

    pair_kernel<<<nP, NT>>>(q, r, u, n, tiles, outscale, out);
}

// round 4
// speedup vs baseline: 1.2691x; 1.2691x over previous
#include <cuda_runtime.h>

#define TI 128
#define NT 512
#define MAX_TILES 64
#define MAX_P (MAX_TILES * (MAX_TILES + 1) / 2)

__device__ double       g_part[MAX_P];
__device__ unsigned int g_count;   // zero at load; last block resets each launch

// SIGMA=1 -> a = 1/sqrt(2), a^2 = 0.5, c = 2a/sqrt(pi)
#define C_CONST  0.79788456080286536f
#define PA_CONST 0.23174530376899319f   /* 0.3275911 * a */

// Per-pair interaction; DIAG controls whether the i==j self-mask is applied.
template<bool DIAG>
__device__ __forceinline__ float pair_term(
    float rix, float riy, float riz, float qi,
    float uix, float uiy, float uiz,
    const float4& rqj, const float4& ujv,
    bool self)
{
    float dx = rqj.x - rix;
    float dy = rqj.y - riy;
    float dz = rqj.z - riz;
    float rsq = fmaf(dx, dx, fmaf(dy, dy, dz * dz));

    if (DIAG) { if (self) rsq = 1.0f; }     // keep math finite; masked below

    float rinv  = rsqrtf(rsq);              // MUFU.RSQ
    float rr    = rsq * rinv;               // |r|
    float gauss = __expf(-0.5f * rsq);      // exp(-(a r)^2) : FMUL + MUFU.EX2

    // Abramowitz-Stegun 7.1.26 (|err| < 1.5e-7), reuses gauss = e^{-x^2};
    // 'a' folded into PA_CONST. __fdividef -> MUFU.RCP (approx), cheap.
    float t = __fdividef(1.0f, fmaf(PA_CONST, rr, 1.0f));
    float poly = fmaf(t, fmaf(t, fmaf(t, fmaf(t, 1.061405429f, -1.453152027f),
                                      1.421413741f), -0.284496736f), 0.254829592f);
    float erfv = fmaf(-t * poly, gauss, 1.0f);

    float rinv2 = rinv * rinv;
    float e1 = erfv * rinv;                          // erf/r
    float e3 = e1 * rinv2;                           // erf/r^3
    float cg = C_CONST * gauss;
    float g2 = cg * rinv2;                           // c*gauss/r^2
    float s1 = e3 - g2;
    float s2 = fmaf(3.0f, e3, fmaf(-2.0f, g2, -cg)); // 3e3 - 2g2 - c*gauss

    float qj  = rqj.w;
    float udi = fmaf(uix, dx, fmaf(uiy, dy, uiz * dz));
    float udj = fmaf(ujv.x, dx, fmaf(ujv.y, dy, ujv.z * dz));
    float uu  = fmaf(uix, ujv.x, fmaf(uiy, ujv.y, uiz * ujv.z));

    float pr = (qi * qj) * e1;                         // qq
    pr = fmaf(-s1, fmaf(qj, udi, -(qi * udj)), pr);    // qu
    pr = fmaf(s1, uu, pr);                             // uu (iso)
    pr = fmaf(-s2, (udi * udj) * rinv2, pr);           // uu (aniso)

    if (DIAG) pr = self ? 0.0f : pr;
    return pr;
}

__global__ void __launch_bounds__(NT, 1) pair_kernel(
    const float* __restrict__ q, const float* __restrict__ r,
    const float* __restrict__ u, int n, int tiles, float outscale,
    float* __restrict__ out)
{
    // ---- triangular tile index -> (bi, bj), bi <= bj ----
    int p = blockIdx.x;
    int bi = 0;
    while (p >= tiles - bi) { p -= tiles - bi; bi++; }
    const int bj = bi + p;
    const bool diag = (bi == bj);

    __shared__ float4 s_rq[TI];   // (x, y, z, q)
    __shared__ float4 s_u[TI];    // (ux, uy, uz, 0)

    const int tx = threadIdx.x;
    const int il = tx & (TI - 1);     // i-lane within tile
    const int jg = tx >> 7;           // j-group 0..3
    const int i  = bi * TI + il;
    const int j0 = bj * TI;

    if (tx < TI) {
        int j = j0 + tx;
        float4 v;
        if (j < n) { v.x = r[3*j]; v.y = r[3*j+1]; v.z = r[3*j+2]; v.w = q[j]; }
        else       { v.x = 1.0e7f + (float)j; v.y = 0.f; v.z = 0.f; v.w = 0.f; }
        s_rq[tx] = v;
    } else if (tx < 2 * TI) {
        int jt = tx - TI;
        int j  = j0 + jt;
        float4 v;
        if (j < n) { v.x = u[3*j]; v.y = u[3*j+1]; v.z = u[3*j+2]; v.w = 0.f; }
        else       { v = make_float4(0.f, 0.f, 0.f, 0.f); }
        s_u[jt] = v;
    }

    float qi = 0.f, rix, riy = 0.f, riz = 0.f, uix = 0.f, uiy = 0.f, uiz = 0.f;
    if (i < n) {
        qi  = q[i];
        rix = r[3*i]; riy = r[3*i+1]; riz = r[3*i+2];
        uix = u[3*i]; uiy = u[3*i+1]; uiz = u[3*i+2];
    } else {
        rix = 2.0e7f + (float)i;   // far, with q=u=0 -> zero contribution
    }
    __syncthreads();

    double acc = 0.0;
    const int jbeg = jg * (TI / 4);    // 32 j's per thread

    if (!diag) {
        #pragma unroll
        for (int g = 0; g < TI / 4; g += 8) {
            float facc = 0.0f;
            #pragma unroll
            for (int k = 0; k < 8; k++) {
                int jj = jbeg + g + k;
                facc += pair_term<false>(rix, riy, riz, qi, uix, uiy, uiz,
                                         s_rq[jj], s_u[jj], false);
            }
            acc += (double)facc;
        }
    } else {
        #pragma unroll
        for (int g = 0; g < TI / 4; g += 8) {
            float facc = 0.0f;
            #pragma unroll
            for (int k = 0; k < 8; k++) {
                int jj = jbeg + g + k;
                facc += pair_term<true>(rix, riy, riz, qi, uix, uiy, uiz,
                                        s_rq[jj], s_u[jj], (j0 + jj) == i);
            }
            acc += (double)facc;
        }
        acc *= 0.5;   // diagonal tile counts each unordered pair twice
    }

    // ---- deterministic block reduction ----
    #pragma unroll
    for (int off = 16; off > 0; off >>= 1)
        acc += __shfl_down_sync(0xffffffffu, acc, off);

    __shared__ double warp_s[NT / 32];
    if ((tx & 31) == 0) warp_s[tx >> 5] = acc;
    __syncthreads();

    __shared__ bool isLast;
    if (tx == 0) {
        double s = 0.0;
        #pragma unroll
        for (int w = 0; w < NT / 32; w++) s += warp_s[w];
        g_part[blockIdx.x] = s;
        __threadfence();
        unsigned c = atomicAdd(&g_count, 1u);
        isLast = (c == gridDim.x - 1);
    }
    __syncthreads();

    // ---- last block: final reduction (fixed order -> deterministic) ----
    if (isLast) {
        __threadfence();
        const int nP = gridDim.x;
        double s = 0.0;
        for (int k = tx; k < nP; k += NT) s += g_part[k];

        #pragma unroll
        for (int off = 16; off > 0; off >>= 1)
            s += __shfl_down_sync(0xffffffffu, s, off);

        __shared__ double fin_s[NT / 32];
        if ((tx & 31) == 0) fin_s[tx >> 5] = s;
        __syncthreads();
        if (tx == 0) {
            double tot = 0.0;
            #pragma unroll
            for (int w = 0; w < NT / 32; w++) tot += fin_s[w];
            out[0] = (float)(tot * (double)outscale);
            g_count = 0;   // reset for next graph replay
        }
    }
}

extern "C" void kernel_launch(void* const* d_in, const int* in_sizes, int n_in,
                              void* d_out, int out_size)
{
    const float* q = (const float*)d_in[0];
    const float* r = (const float*)d_in[1];
    const float* u = (const float*)d_in[2];
    float* out = (float*)d_out;

    int n = in_sizes[0];
    int tiles = (n + TI - 1) / TI;
    if (tiles > MAX_TILES) tiles = MAX_TILES;

    int nP = tiles * (tiles + 1) / 2;
    float outscale = (float)(90.0474 / 6.283185307179586476925286766559);

    pair_kernel<<<nP, NT>>>(q, r, u, n, tiles, outscale, out);
}

// round 6
// speedup vs baseline: 1.2854x; 1.0129x over previous
#include <cuda_runtime.h>

#define TI 128
#define NT 512
#define MAX_TILES 64
#define MAX_P (MAX_TILES * (MAX_TILES + 1) / 2)

__device__ double       g_part[MAX_P];
__device__ unsigned int g_count;   // zero at load; last block resets each launch

// SIGMA=1 -> a=1/sqrt(2), c=2a/sqrt(pi).  KEXP = -0.5*log2(e)
#define C_CONST   0.79788456080286536f
#define PA_CONST  0.23174530376899319f   /* 0.3275911 * a */
#define KEXP     -0.72134752044448170f

typedef unsigned long long u64;
struct F2 { u64 v; };

__device__ __forceinline__ F2 pack2(float lo, float hi) {
    F2 r; asm("mov.b64 %0,{%1,%2};" : "=l"(r.v) : "f"(lo), "f"(hi)); return r;
}
__device__ __forceinline__ void unpack2(F2 a, float& lo, float& hi) {
    asm("mov.b64 {%0,%1},%2;" : "=f"(lo), "=f"(hi) : "l"(a.v));
}
__device__ __forceinline__ F2 add2(F2 a, F2 b) {
    F2 r; asm("add.rn.f32x2 %0,%1,%2;" : "=l"(r.v) : "l"(a.v), "l"(b.v)); return r;
}
__device__ __forceinline__ F2 mul2(F2 a, F2 b) {
    F2 r; asm("mul.rn.f32x2 %0,%1,%2;" : "=l"(r.v) : "l"(a.v), "l"(b.v)); return r;
}
__device__ __forceinline__ F2 fma2(F2 a, F2 b, F2 c) {
    F2 r; asm("fma.rn.f32x2 %0,%1,%2,%3;" : "=l"(r.v) : "l"(a.v), "l"(b.v), "l"(c.v)); return r;
}
__device__ __forceinline__ float ex2f(float x)  { float r; asm("ex2.approx.f32 %0,%1;"   : "=f"(r) : "f"(x)); return r; }
__device__ __forceinline__ float rcpf(float x)  { float r; asm("rcp.approx.f32 %0,%1;"   : "=f"(r) : "f"(x)); return r; }
__device__ __forceinline__ float rsqf(float x)  { float r; asm("rsqrt.approx.f32 %0,%1;" : "=f"(r) : "f"(x)); return r; }

__global__ void __launch_bounds__(NT, 1) pair_kernel(
    const float* __restrict__ q, const float* __restrict__ r,
    const float* __restrict__ u, int n, int tiles, float outscale,
    float* __restrict__ out)
{
    // ---- triangular tile index -> (bi, bj), bi <= bj ----
    int p = blockIdx.x;
    int bi = 0;
    while (p >= tiles - bi) { p -= tiles - bi; bi++; }
    const int bj = bi + p;
    const bool diag = (bi == bj);

    // SoA j-tile in shared memory (float2-loadable)
    __shared__ __align__(16) float s_x[TI], s_y[TI], s_z[TI], s_q[TI];
    __shared__ __align__(16) float s_ux[TI], s_uy[TI], s_uz[TI];

    const int tx = threadIdx.x;
    const int il = tx & (TI - 1);     // i-lane within tile
    const int jg = tx >> 7;           // j-group 0..3
    const int i  = bi * TI + il;
    const int j0 = bj * TI;

    if (tx < TI) {
        int j = j0 + tx;
        if (j < n) {
            s_x[tx] = r[3*j]; s_y[tx] = r[3*j+1]; s_z[tx] = r[3*j+2]; s_q[tx] = q[j];
        } else {
            s_x[tx] = 1.0e7f + (float)j; s_y[tx] = 0.f; s_z[tx] = 0.f; s_q[tx] = 0.f;
        }
    } else if (tx < 2 * TI) {
        int jt = tx - TI, j = j0 + jt;
        if (j < n) { s_ux[jt] = u[3*j]; s_uy[jt] = u[3*j+1]; s_uz[jt] = u[3*j+2]; }
        else       { s_ux[jt] = 0.f; s_uy[jt] = 0.f; s_uz[jt] = 0.f; }
    }

    float qi = 0.f, rix, riy = 0.f, riz = 0.f, uix = 0.f, uiy = 0.f, uiz = 0.f;
    if (i < n) {
        qi  = q[i];
        rix = r[3*i]; riy = r[3*i+1]; riz = r[3*i+2];
        uix = u[3*i]; uiy = u[3*i+1]; uiz = u[3*i+2];
    } else {
        rix = 2.0e7f + (float)i;   // far, q=u=0 -> zero contribution
    }
    __syncthreads();

    // Broadcast-packed per-thread constants
    const F2 nrix2 = pack2(-rix, -rix), nriy2 = pack2(-riy, -riy), nriz2 = pack2(-riz, -riz);
    const F2 uix2  = pack2(uix, uix),   uiy2  = pack2(uiy, uiy),   uiz2  = pack2(uiz, uiz);
    const F2 qi2   = pack2(qi, qi),     nqi2  = pack2(-qi, -qi);
    const F2 ONE2  = pack2(1.0f, 1.0f), NEG1  = pack2(-1.0f, -1.0f);
    const F2 PA2   = pack2(PA_CONST, PA_CONST);
    const F2 NEGC  = pack2(-C_CONST, -C_CONST);
    const F2 PC1 = pack2(0.254829592f, 0.254829592f);
    const F2 PC2 = pack2(-0.284496736f, -0.284496736f);
    const F2 PC3 = pack2(1.421413741f, 1.421413741f);
    const F2 PC4 = pack2(-1.453152027f, -1.453152027f);
    const F2 PC5 = pack2(1.061405429f, 1.061405429f);

    const float2* sx2  = reinterpret_cast<const float2*>(s_x);
    const float2* sy2  = reinterpret_cast<const float2*>(s_y);
    const float2* sz2  = reinterpret_cast<const float2*>(s_z);
    const float2* sq2  = reinterpret_cast<const float2*>(s_q);
    const float2* sux2 = reinterpret_cast<const float2*>(s_ux);
    const float2* suy2 = reinterpret_cast<const float2*>(s_uy);
    const float2* suz2 = reinterpret_cast<const float2*>(s_uz);

    double acc = 0.0;
    const int jp0 = jg * (TI / 8);    // 16 float2 slots (32 j's) per thread

    #pragma unroll
    for (int g = 0; g < TI / 8; g += 4) {
        F2 faccp = pack2(0.f, 0.f);
        #pragma unroll
        for (int k = 0; k < 4; k++) {
            const int jp = jp0 + g + k;     // float2 slot; j = j0 + 2*jp (+1)
            float2 xj = sx2[jp], yj = sy2[jp], zj = sz2[jp], qjv = sq2[jp];
            float2 uxj = sux2[jp], uyj = suy2[jp], uzj = suz2[jp];
            F2 xjp = pack2(xj.x, xj.y), yjp = pack2(yj.x, yj.y), zjp = pack2(zj.x, zj.y);
            F2 qjp = pack2(qjv.x, qjv.y);
            F2 uxp = pack2(uxj.x, uxj.y), uyp = pack2(uyj.x, uyj.y), uzp = pack2(uzj.x, uzj.y);

            F2 dx = add2(xjp, nrix2);
            F2 dy = add2(yjp, nriy2);
            F2 dz = add2(zjp, nriz2);
            F2 rsqp = fma2(dx, dx, fma2(dy, dy, mul2(dz, dz)));

            float rsq0, rsq1; unpack2(rsqp, rsq0, rsq1);
            bool self0 = false, self1 = false;
            if (diag) {
                self0 = (j0 + 2*jp     == i);
                self1 = (j0 + 2*jp + 1 == i);
                if (self0) rsq0 = 1.0f;
                if (self1) rsq1 = 1.0f;
                rsqp = pack2(rsq0, rsq1);
            }

            // scalar MUFU block (rsq -> rinv, gauss)
            float rinv0 = rsqf(rsq0), rinv1 = rsqf(rsq1);
            float ga0 = ex2f(rsq0 * KEXP), ga1 = ex2f(rsq1 * KEXP);
            F2 rinvp  = pack2(rinv0, rinv1);
            F2 gaussp = pack2(ga0, ga1);

            // erf via A&S 7.1.26 (packed), t = 1/(1 + pa*|r|)
            F2 rrp  = mul2(rsqp, rinvp);
            F2 tden = fma2(rrp, PA2, ONE2);
            float td0, td1; unpack2(tden, td0, td1);
            F2 tp = pack2(rcpf(td0), rcpf(td1));
            F2 polyp = fma2(tp, fma2(tp, fma2(tp, fma2(tp, PC5, PC4), PC3), PC2), PC1);
            F2 wp   = mul2(mul2(tp, polyp), gaussp);     // t*poly*gauss
            F2 erfp = fma2(wp, NEG1, ONE2);              // 1 - w

            F2 e1p    = mul2(erfp, rinvp);
            F2 rinv2p = mul2(rinvp, rinvp);
            F2 e3p    = mul2(e1p, rinv2p);
            F2 ncgp   = mul2(gaussp, NEGC);              // -c*gauss
            F2 g2np   = mul2(ncgp, rinv2p);              // -c*gauss/r^2
            F2 s1p    = add2(e3p, g2np);
            // s2 = 3e3 - 2g2 - cg = 2*s1 + e3 + ncg
            F2 s2p = add2(add2(s1p, s1p), add2(e3p, ncgp));

            F2 udip = fma2(uix2, dx, fma2(uiy2, dy, mul2(uiz2, dz)));
            F2 udjp = fma2(uxp,  dx, fma2(uyp,  dy, mul2(uzp,  dz)));
            F2 uup  = fma2(uix2, uxp, fma2(uiy2, uyp, mul2(uiz2, uzp)));

            F2 prp   = mul2(mul2(qjp, qi2), e1p);                  // qq
            F2 inner = fma2(qjp, udip, mul2(nqi2, udjp));          // qj*udi - qi*udj
            prp = fma2(mul2(s1p, NEG1), inner, prp);               // qu
            prp = fma2(s1p, uup, prp);                             // uu iso
            F2 m2 = mul2(mul2(udip, udjp), rinv2p);
            prp = fma2(mul2(s2p, NEG1), m2, prp);                  // uu aniso

            if (diag && (self0 || self1)) {
                float p0, p1; unpack2(prp, p0, p1);
                if (self0) p0 = 0.f;
                if (self1) p1 = 0.f;
                prp = pack2(p0, p1);
            }
            faccp = add2(faccp, prp);
        }
        float f0, f1; unpack2(faccp, f0, f1);
        acc += (double)(f0 + f1);
    }

    if (diag) acc *= 0.5;   // diagonal tile counts each unordered pair twice

    // ---- deterministic block reduction ----
    #pragma unroll
    for (int off = 16; off > 0; off >>= 1)
        acc += __shfl_down_sync(0xffffffffu, acc, off);

    __shared__ double warp_s[NT / 32];
    if ((tx & 31) == 0) warp_s[tx >> 5] = acc;
    __syncthreads();

    __shared__ bool isLast;
    if (tx == 0) {
        double s = 0.0;
        #pragma unroll
        for (int w = 0; w < NT / 32; w++) s += warp_s[w];
        g_part[blockIdx.x] = s;
        __threadfence();
        unsigned c = atomicAdd(&g_count, 1u);
        isLast = (c == gridDim.x - 1);
    }
    __syncthreads();

    // ---- last block: final reduction (fixed order -> deterministic) ----
    if (isLast) {
        __threadfence();
        const int nP = gridDim.x;
        double s = 0.0;
        for (int k = tx; k < nP; k += NT) s += g_part[k];

        #pragma unroll
        for (int off = 16; off > 0; off >>= 1)
            s += __shfl_down_sync(0xffffffffu, s, off);

        __shared__ double fin_s[NT / 32];
        if ((tx & 31) == 0) fin_s[tx >> 5] = s;
        __syncthreads();
        if (tx == 0) {
            double tot = 0.0;
            #pragma unroll
            for (int w = 0; w < NT / 32; w++) tot += fin_s[w];
            out[0] = (float)(tot * (double)outscale);
            g_count = 0;   // reset for next graph replay
        }
    }
}

extern "C" void kernel_launch(void* const* d_in, const int* in_sizes, int n_in,
                              void* d_out, int out_size)
{
    const float* q = (const float*)d_in[0];
    const float* r = (const float*)d_in[1];
    const float* u = (const float*)d_in[2];
    float* out = (float*)d_out;

    int n = in_sizes[0];
    int tiles = (n + TI - 1) / TI;
    if (tiles > MAX_TILES) tiles = MAX_TILES;

    int nP = tiles * (tiles + 1) / 2;
    float outscale = (float)(90.0474 / 6.283185307179586476925286766559);

    pair_kernel<<<nP, NT>>>(q, r, u, n, tiles, outscale, out);
}